// round 11
// baseline (speedup 1.0000x reference)
#include <cuda_runtime.h>
#include <cuda_bf16.h>
#include <cstdint>

// CRF log-likelihood: B=256, M=1024, D=128, N=26.
// Fused design:
//   crf_fused (512 blocks, 160 thr): block (seq, half).  4 producer warps
//     compute emission tiles (HMMA bf16, A direct from X) into smem double
//     buffer + accumulate unnormalized score; 1 scanner warp runs the
//     forward (even block) or adjoint (odd block) recurrence off smem tiles.
//     No g_e global array at all.
//   combine (1 block): per-seq dot(v,u) + boundary transition + mean.

#define B_ 256
#define M_ 1024
#define D_ 128
#define N_ 26
#define FULLM 0xffffffffu
#define XS 136                         // bf16 row stride for Wb smem
#define ES 36                          // f32 row stride for e tiles
typedef unsigned long long ull;

__device__ float g_midv[B_ * 32];      // v_511 per seq
__device__ float g_midu[B_ * 32];      // u_511 per seq
__device__ float g_cfw[B_];            // fwd log2 scale
__device__ float g_cbw[B_];            // bwd log2 scale
__device__ float g_sc[2 * B_];         // per-block score partials

__device__ __forceinline__ uint32_t bf2(float x, float y) {
    uint32_t p;
    asm("cvt.rn.bf16x2.f32 %0, %1, %2;" : "=r"(p) : "f"(y), "f"(x));
    return p;
}
__device__ __forceinline__ ull fma2(ull a, ull b, ull c) {
    ull d;
    asm("fma.rn.f32x2 %0, %1, %2, %3;" : "=l"(d) : "l"(a), "l"(b), "l"(c));
    return d;
}
__device__ __forceinline__ ull packf2(float lo, float hi) {
    return (ull)__float_as_uint(lo) | ((ull)__float_as_uint(hi) << 32);
}
__device__ __forceinline__ void mma_bf16(float* d, const uint32_t* a,
                                         const uint32_t* b) {
    asm volatile(
        "mma.sync.aligned.m16n8k16.row.col.f32.bf16.bf16.f32 "
        "{%0,%1,%2,%3}, {%4,%5,%6,%7}, {%8,%9}, {%0,%1,%2,%3};"
        : "+f"(d[0]), "+f"(d[1]), "+f"(d[2]), "+f"(d[3])
        : "r"(a[0]), "r"(a[1]), "r"(a[2]), "r"(a[3]), "r"(b[0]), "r"(b[1]));
}

// 26-dot of broadcast state (7x ulonglong2 = 28 floats, 26 valid) with
// packed per-lane coefficients; 13 f32x2 FMAs in 2 chains.
__device__ __forceinline__ float dot26p(const ulonglong2 t2[7], const ull* E2) {
    ull a0 = 0ull, a1 = 0ull;
    a0 = fma2(t2[0].x, E2[0], a0);  a1 = fma2(t2[0].y, E2[1], a1);
    a0 = fma2(t2[1].x, E2[2], a0);  a1 = fma2(t2[1].y, E2[3], a1);
    a0 = fma2(t2[2].x, E2[4], a0);  a1 = fma2(t2[2].y, E2[5], a1);
    a0 = fma2(t2[3].x, E2[6], a0);  a1 = fma2(t2[3].y, E2[7], a1);
    a0 = fma2(t2[4].x, E2[8], a0);  a1 = fma2(t2[4].y, E2[9], a1);
    a0 = fma2(t2[5].x, E2[10], a0); a1 = fma2(t2[5].y, E2[11], a1);
    a0 = fma2(t2[6].x, E2[12], a0);        // labels 24,25; skip garbage pair
    float l0 = __int_as_float((int)(a0 & 0xffffffffull));
    float h0 = __int_as_float((int)(a0 >> 32));
    float l1 = __int_as_float((int)(a1 & 0xffffffffull));
    float h1 = __int_as_float((int)(a1 >> 32));
    return (l0 + h0) + (l1 + h1);
}

// producer: compute one 32-row warp-slice of a 128-row e tile into et smem
__device__ __forceinline__ void produce_slice(const float* __restrict__ X,
                                              const __nv_bfloat16* Wb,
                                              float* et, size_t rowbase_g,
                                              int warp, int lane) {
    const int q = lane & 3, r8 = lane >> 2;
    const size_t wrow = rowbase_g + warp * 32;

    float acc[2][4][4];
#pragma unroll
    for (int mt = 0; mt < 2; mt++)
#pragma unroll
        for (int nt = 0; nt < 4; nt++)
#pragma unroll
            for (int e = 0; e < 4; e++) acc[mt][nt][e] = 0.f;

#pragma unroll
    for (int ks = 0; ks < 8; ks++) {
        const int k0 = ks * 16;
        uint32_t afrag[2][4], bfrag[4][2];
#pragma unroll
        for (int mt = 0; mt < 2; mt++) {
            const float* xr  = X + (wrow + mt * 16 + r8) * D_;
            const float* xr8 = xr + 8 * D_;
            float2 v0 = __ldg((const float2*)(xr  + k0 + 2 * q));
            float2 v1 = __ldg((const float2*)(xr8 + k0 + 2 * q));
            float2 v2 = __ldg((const float2*)(xr  + k0 + 8 + 2 * q));
            float2 v3 = __ldg((const float2*)(xr8 + k0 + 8 + 2 * q));
            afrag[mt][0] = bf2(v0.x, v0.y);
            afrag[mt][1] = bf2(v1.x, v1.y);
            afrag[mt][2] = bf2(v2.x, v2.y);
            afrag[mt][3] = bf2(v3.x, v3.y);
        }
#pragma unroll
        for (int nt = 0; nt < 4; nt++) {
            const int n = nt * 8 + r8;
            bfrag[nt][0] = *(const uint32_t*)&Wb[n * XS + k0 + 2 * q];
            bfrag[nt][1] = *(const uint32_t*)&Wb[n * XS + k0 + 8 + 2 * q];
        }
#pragma unroll
        for (int mt = 0; mt < 2; mt++)
#pragma unroll
            for (int nt = 0; nt < 4; nt++)
                mma_bf16(acc[mt][nt], afrag[mt], bfrag[nt]);
    }
    // store C to the e tile (local rows warp*32 + ...)
#pragma unroll
    for (int mt = 0; mt < 2; mt++)
#pragma unroll
        for (int nt = 0; nt < 4; nt++) {
            const int rl = warp * 32 + mt * 16 + r8;
            const int c  = nt * 8 + 2 * q;
            *(float2*)&et[rl * ES + c] =
                make_float2(acc[mt][nt][0], acc[mt][nt][1]);
            *(float2*)&et[(rl + 8) * ES + c] =
                make_float2(acc[mt][nt][2], acc[mt][nt][3]);
        }
}

// ---------------------------------------------------------------------------
__global__ __launch_bounds__(160) void crf_fused(const float* __restrict__ X,
                                                 const int* __restrict__ labels,
                                                 const float* __restrict__ W,
                                                 const float* __restrict__ Tg) {
    __shared__ __nv_bfloat16 Wb[32 * XS];                 // 8704 B
    __shared__ float et[2][128 * ES];                      // 36864 B
    __shared__ __align__(16) float vxch[2][32];
    __shared__ float s_part[4];

    const int tid  = threadIdx.x;
    const int warp = tid >> 5;
    const int lane = tid & 31;
    const int bid  = blockIdx.x;
    const int seq  = bid >> 1;
    const int bwd  = bid & 1;
    const int halfOff = bwd ? 512 : 0;
    const int* lab = labels + seq * M_;

    // stage W (bf16, rows >=26 zero)
    for (int i = tid; i < 1024; i += 160) {
        const int row = i >> 5, c4 = i & 31;
        float4 v = make_float4(0.f, 0.f, 0.f, 0.f);
        if (row < N_) v = __ldg((const float4*)(W + row * D_) + c4);
        uint2 p = make_uint2(bf2(v.x, v.y), bf2(v.z, v.w));
        *(uint2*)&Wb[row * XS + c4 * 4] = p;
    }
    __syncthreads();

    // persistent state
    float scAcc = 0.f;                 // producers
    float vstate = 0.f, Cl2 = 0.f;     // scanner
    int par = 0, rc = 0;
    ull ET2[13];

    if (warp < 4) {
        // produce tile p=0  (global tile: fwd->0, bwd->3)
        const int t0g = bwd ? 3 : 0;
        produce_slice(X, Wb, et[0],
                      (size_t)seq * M_ + halfOff + t0g * 128, warp, lane);
    } else {
        // scanner: load packed transition coefficients
        const int la = lane < N_ ? lane : 25;
#pragma unroll
        for (int i = 0; i < 13; i++) {
            float lo, hi;
            if (!bwd) {                // ETc[b] = exp(T[b][lane]) (column)
                lo = __expf(__ldg(Tg + (2 * i) * 26 + la));
                hi = __expf(__ldg(Tg + (2 * i + 1) * 26 + la));
            } else {                   // ETr[a] = exp(T[lane][a]) (row)
                lo = __expf(__ldg(Tg + la * 26 + 2 * i));
                hi = __expf(__ldg(Tg + la * 26 + 2 * i + 1));
            }
            ET2[i] = packf2(lo, hi);
        }
    }
    __syncthreads();

    for (int t = 0; t < 4; t++) {
        if (warp < 4) {
            // produce next tile into the other buffer
            if (t < 3) {
                const int pg = bwd ? (3 - (t + 1)) : (t + 1);
                produce_slice(X, Wb, et[(t + 1) & 1],
                              (size_t)seq * M_ + halfOff + pg * 128, warp, lane);
            }
            // score tile t (rows in buffer t&1)
            {
                const int tg   = bwd ? (3 - t) : t;
                const int mloc = halfOff + tg * 128 + warp * 32 + lane;
                const int y    = __ldg(lab + mloc);
                float se = et[t & 1][(warp * 32 + lane) * ES + y];
                float st = 0.f;
                if (mloc < halfOff + 511) {
                    const int yn = __ldg(lab + mloc + 1);
                    st = __ldg(Tg + y * 26 + yn);
                }
                scAcc += se + st;
            }
        } else {
            const float* etb = et[t & 1];
            if (!bwd) {
                // ---------------- forward ----------------
                int r0;
                float Ecur;
                if (t == 0) {
                    vstate = __expf(etb[lane]);            // v_0 = exp(e_0)
                    vxch[0][lane] = vstate;
                    __syncwarp();
                    Ecur = __expf(etb[1 * ES + lane]);
                    r0 = 1;
                } else {
                    Ecur = __expf(etb[lane]);
                    r0 = 0;
                }
                for (int r = r0; r < 128; r++) {
                    float Enext = (r < 127) ? __expf(etb[(r + 1) * ES + lane]) : 0.f;
                    ulonglong2 t2[7];
                    const ulonglong2* vp = (const ulonglong2*)&vxch[par][0];
#pragma unroll
                    for (int qq = 0; qq < 7; qq++) t2[qq] = vp[qq];
                    vstate = Ecur * dot26p(t2, ET2);
                    Ecur = Enext;
                    if (((++rc) & 7) == 0) {
                        float pf = __int_as_float((int)(t2[0].x & 0xffffffffull));
                        int ex = (__float_as_int(pf) >> 23) - 127;
                        Cl2 += (float)ex;
                        vstate = __int_as_float(__float_as_int(vstate) - (ex << 23));
                    }
                    vxch[par ^ 1][lane] = vstate;
                    __syncwarp();
                    par ^= 1;
                }
            } else {
                // ---------------- adjoint (backward) ----------------
                int rhi;
                if (t == 0) {
                    float E0 = __expf(etb[127 * ES + lane]); // E_1023
                    vxch[0][lane] = E0;                       // s_1023
                    __syncwarp();
                    rhi = 126;
                } else {
                    rhi = 127;
                }
                for (int r = rhi; r >= 0; r--) {
                    float Estore = __expf(etb[r * ES + lane]);  // E_{m-1}
                    ulonglong2 t2[7];
                    const ulonglong2* vp = (const ulonglong2*)&vxch[par][0];
#pragma unroll
                    for (int qq = 0; qq < 7; qq++) t2[qq] = vp[qq];
                    float u = dot26p(t2, ET2);
                    if (((++rc) & 7) == 0) {
                        float pf = __int_as_float((int)(t2[0].x & 0xffffffffull));
                        int ex = (__float_as_int(pf) >> 23) - 127;
                        Cl2 += (float)ex;
                        u = __int_as_float(__float_as_int(u) - (ex << 23));
                    }
                    vstate = u;
                    vxch[par ^ 1][lane] = Estore * u;
                    __syncwarp();
                    par ^= 1;
                }
                if (t == 3) {
                    // final dot: u_511 from s_512
                    ulonglong2 t2[7];
                    const ulonglong2* vp = (const ulonglong2*)&vxch[par][0];
#pragma unroll
                    for (int qq = 0; qq < 7; qq++) t2[qq] = vp[qq];
                    vstate = dot26p(t2, ET2);
                }
            }
        }
        __syncthreads();
    }

    // epilogue
    if (warp < 4) {
#pragma unroll
        for (int off = 16; off; off >>= 1)
            scAcc += __shfl_xor_sync(FULLM, scAcc, off);
        if (lane == 0) s_part[warp] = scAcc;
    } else {
        if (lane < N_) {
            if (!bwd) g_midv[seq * 32 + lane] = vstate;
            else      g_midu[seq * 32 + lane] = vstate;
        }
        if (lane == 0) {
            if (!bwd) g_cfw[seq] = Cl2;
            else      g_cbw[seq] = Cl2;
        }
    }
    __syncthreads();
    if (tid == 0)
        g_sc[bid] = s_part[0] + s_part[1] + s_part[2] + s_part[3];
}

// ---------------------------------------------------------------------------
// combine: per-seq bilinear form + boundary transition + mean -> out[0]
// ---------------------------------------------------------------------------
__global__ __launch_bounds__(256) void combine(const int* __restrict__ labels,
                                               const float* __restrict__ Tg,
                                               float* __restrict__ out) {
    const int s = threadIdx.x;

    float pv = 0.f;
#pragma unroll
    for (int a = 0; a < N_; a++)
        pv += g_midv[s * 32 + a] * g_midu[s * 32 + a];

    const int y0 = __ldg(labels + s * M_ + 511);
    const int y1 = __ldg(labels + s * M_ + 512);
    float sc = g_sc[2 * s] + g_sc[2 * s + 1] + __ldg(Tg + y0 * 26 + y1);

    const float LN2 = 0.6931471805599453f;
    float res = sc - (g_cfw[s] + g_cbw[s]) * LN2 - __logf(pv);

#pragma unroll
    for (int off = 16; off; off >>= 1)
        res += __shfl_xor_sync(FULLM, res, off);

    __shared__ float sh[8];
    if ((s & 31) == 0) sh[s >> 5] = res;
    __syncthreads();
    if (s < 8) {
        float tt = sh[s];
#pragma unroll
        for (int off = 4; off; off >>= 1)
            tt += __shfl_xor_sync(0xffu, tt, off);
        if (s == 0) out[0] = tt * (1.0f / 256.0f);
    }
}

// ---------------------------------------------------------------------------
extern "C" void kernel_launch(void* const* d_in, const int* in_sizes, int n_in,
                              void* d_out, int out_size) {
    const float* X      = (const float*)d_in[0];   // [256,1024,128] f32
    const int*   labels = (const int*)d_in[1];     // [256,1024] i32
    const float* W      = (const float*)d_in[2];   // [26,128] f32
    const float* Tm     = (const float*)d_in[3];   // [26,26] f32

    crf_fused<<<2 * B_, 160>>>(X, labels, W, Tm);
    combine<<<1, 256>>>(labels, Tm, (float*)d_out);
}